// round 14
// baseline (speedup 1.0000x reference)
#include <cuda_runtime.h>
#include <cuda_bf16.h>

// ---------------- problem constants (from reference setup_inputs) ----------------
constexpr int B = 64;
constexpr int P = 24576;
constexpr int C = 81;            // NUM_CLASSES + 1
constexpr int NEG_POS_RATIO = 3;

constexpr int TPB = 128;                 // threads per block
constexpr int APB = 64;                  // anchors per tile (2 lanes/anchor: even/odd pair)
constexpr int NT  = (B * P) / APB;       // 24576 tiles
constexpr int TPI = P / APB;             // 384 tiles per image (tiles never straddle images)
constexpr int TILE_F  = APB * C;         // 5184 floats per tile
constexpr int TILE_F4 = TILE_F / 4;      // 1296 float4
constexpr int NBLK = 740;                // persistent CTAs: 148 SMs x 5 (exactly one wave)
constexpr int NW   = TPB / 32;           // 4 warps -> 4 partial slots per tile

// ---------------- scratch (device globals; no allocation allowed) ----------------
__device__ float g_ce_neg[B * P];   // CE for negatives, 0 for positives (fallback path)
__device__ float g_pos[NT * NW];    // per-warp-per-tile positive loss  [distinct addrs]
__device__ float g_negp[NT * NW];   // per-warp-per-tile negative-CE sum
__device__ int   g_cnt[NT * NW];    // per-warp-per-tile positive counts
__device__ float g_img_loss[B];
__device__ int   g_img_pos[B];
__device__ int   g_tile_ctr;        // work-stealing ticket (reset each run)
__device__ int   g_done;            // phase-1 arrival ticket (reset each run)
__device__ int   g_done2;           // phase-2 arrival ticket (reset each run)

// ---------------- helpers ----------------
__device__ __forceinline__ float huber1(float d) {
    float ad = fabsf(d);
    return ad < 1.0f ? 0.5f * d * d : ad - 0.5f;
}
__device__ __forceinline__ void cp_async16(void* smem_dst, const void* gmem_src) {
    unsigned sa = (unsigned)__cvta_generic_to_shared(smem_dst);
    asm volatile("cp.async.cg.shared.global [%0], [%1], 16;" :: "r"(sa), "l"(gmem_src));
}
__device__ __forceinline__ void cp_commit() { asm volatile("cp.async.commit_group;"); }
__device__ __forceinline__ void cp_wait1()  { asm volatile("cp.async.wait_group 1;"); }

// ---------------- single persistent kernel -----------------------------------------
__global__ void __launch_bounds__(TPB) k_ssd(
    const float* __restrict__ loc_preds,
    const float* __restrict__ cls_preds,
    const float* __restrict__ loc_targets,
    const int*   __restrict__ cls_targets,
    float* __restrict__ out)
{
    __shared__ float buf[2][TILE_F];     // 2 x 20736 B
    __shared__ int   s_tgt[2][APB];
    __shared__ int   s_nt[2];            // prefetched work tickets
    __shared__ int   s_last;

    const int tid  = threadIdx.x;
    const int lane = tid & 31;
    const int wid  = tid >> 5;
    const int pr   = tid >> 1;           // anchor within tile (pair index)
    const int odd  = tid & 1;            // class-half: even -> [0,41), odd -> [41,81)
    const int base = odd * 41;

    auto stage = [&](int tile, int s) {
        const float4* __restrict__ src =
            reinterpret_cast<const float4*>(cls_preds + (long)tile * TILE_F);
        float4* dst = reinterpret_cast<float4*>(buf[s]);
        #pragma unroll
        for (int it = 0; it < 10; it++)            // 10 full rounds: 1280 float4
            cp_async16(&dst[tid + it * TPB], &src[tid + it * TPB]);
        if (tid < TILE_F4 - 10 * TPB)              // 16-thread tail
            cp_async16(&dst[tid + 10 * TPB], &src[tid + 10 * TPB]);
        else if (tid >= 112 && tid < 112 + APB / 4) {  // 16 threads stage targets
            int i = tid - 112;
            const int4* ts = reinterpret_cast<const int4*>(cls_targets + (long)tile * APB);
            cp_async16(&reinterpret_cast<int4*>(s_tgt[s])[i], &ts[i]);
        }
    };

    // ---- grab first two work tickets ----
    if (tid == 0) {
        s_nt[0] = atomicAdd(&g_tile_ctr, 1);
        s_nt[1] = atomicAdd(&g_tile_ctr, 1);
    }
    __syncthreads();
    int t_cur  = s_nt[0];
    int t_next = s_nt[1];

    if (t_cur < NT) stage(t_cur, 0);
    cp_commit();

    int cur = 0;
    while (t_cur < NT) {
        if (t_next < NT) stage(t_next, cur ^ 1);
        cp_commit();
        cp_wait1();
        __syncthreads();                            // tile resident for all threads

        const long ag = (long)t_cur * APB + pr;
        const int t = s_tgt[cur][pr];

        // even lane of each pair loads loc data (predicated; fully coalesced)
        float4 lp, lt;
        if (!odd) {
            lp = reinterpret_cast<const float4*>(loc_preds)[ag];
            lt = reinterpret_cast<const float4*>(loc_targets)[ag];
        }

        // half-row exp sums; lane-uniform loop (base differs per lane, no divergence)
        const float* __restrict__ row = buf[cur] + pr * C;
        float e0 = 0.0f, e1 = 0.0f;
        #pragma unroll
        for (int i = 0; i < 40; i += 2) {
            e0 += __expf(row[base + i]);
            e1 += __expf(row[base + i + 1]);
        }
        if (!odd) e0 += __expf(row[40]);            // even half has 41 classes
        float e = e0 + e1;
        e += __shfl_xor_sync(0xFFFFFFFFu, e, 1);    // combine pair halves

        // target logit: owning lane contributes, partner adds 0
        const bool own = (odd == (t > 40));
        float cand = own ? row[t] : 0.0f;
        const float xt = cand + __shfl_xor_sync(0xFFFFFFFFu, cand, 1);

        const float ce = __logf(e) - xt;

        float accp = 0.0f, accn = 0.0f;
        int cnt = 0;
        if (!odd) {                                  // even lane owns the anchor's result
            const bool pos = (t > 0);
            g_ce_neg[ag] = pos ? 0.0f : ce;
            if (pos) {
                accp = ce + huber1(lp.x - lt.x) + huber1(lp.y - lt.y) +
                            huber1(lp.z - lt.z) + huber1(lp.w - lt.w);
                cnt = 1;
            } else {
                accn = ce;
            }
        }
        // warp reduction (odd lanes contribute zeros)
        #pragma unroll
        for (int o = 16; o; o >>= 1) {
            accp += __shfl_down_sync(0xFFFFFFFFu, accp, o);
            accn += __shfl_down_sync(0xFFFFFFFFu, accn, o);
            cnt  += __shfl_down_sync(0xFFFFFFFFu, cnt,  o);
        }
        if (lane == 0) {                             // distinct addresses: plain stores
            g_pos[t_cur * NW + wid]  = accp;
            g_negp[t_cur * NW + wid] = accn;
            g_cnt[t_cur * NW + wid]  = cnt;
        }

        // fetch the next-next ticket; trailing sync publishes it and also
        // guarantees buf[cur] is free before the next stage overwrites it
        if (tid == 0 && t_next < NT) s_nt[0] = atomicAdd(&g_tile_ctr, 1);
        __syncthreads();
        t_cur  = t_next;
        t_next = s_nt[0];
        cur ^= 1;
    }

    // ---- phase-1 ticket: all CTAs announce completion ----
    if (tid == 0) {
        __threadfence();
        atomicAdd(&g_done, 1);
    }
    if (blockIdx.x >= B) return;                     // only CTAs 0..63 continue

    // ---- grid barrier (safe: single wave, all 740 CTAs resident) ----
    if (tid == 0) {
        while (atomicAdd(&g_done, 0) < NBLK) { }
        __threadfence();
    }
    __syncthreads();

    // ================= per-image epilogue: CTA b handles image b =================
    const int b = blockIdx.x;

    __shared__ float sf[TPB];
    __shared__ float sn[TPB];
    __shared__ int   si[TPB];
    __shared__ unsigned s_bits;

    float p = 0.0f, n = 0.0f; int c = 0;
    #pragma unroll
    for (int i = tid; i < TPI * NW; i += TPB) {      // 12 iterations, L2-hot
        int idx = b * TPI * NW + i;
        p += g_pos[idx]; n += g_negp[idx]; c += g_cnt[idx];
    }
    sf[tid] = p; sn[tid] = n; si[tid] = c; __syncthreads();
    #pragma unroll
    for (int o = TPB / 2; o; o >>= 1) {
        if (tid < o) { sf[tid] += sf[tid + o]; sn[tid] += sn[tid + o]; si[tid] += si[tid + o]; }
        __syncthreads();
    }
    const float pos_loss = sf[0];
    float neg = sn[0];
    const int np = si[0];
    __syncthreads();

    const long negc = (long)P - np;
    const long k = min((long)NEG_POS_RATIO * (long)np, negc);

    if (k < negc) {   // general path (not taken on this data); exact tie-corrected top-k
        const float* row = g_ce_neg + (size_t)b * P;
        if (k <= 0) {
            neg = 0.0f;
        } else {
            float m = 0.0f;
            for (int i = tid; i < P; i += TPB) m = fmaxf(m, row[i]);
            sf[tid] = m; __syncthreads();
            for (int o = TPB / 2; o; o >>= 1) { if (tid < o) sf[tid] = fmaxf(sf[tid], sf[tid + o]); __syncthreads(); }
            m = sf[0];
            __syncthreads();

            unsigned lo = 0u, hi = __float_as_uint(fmaxf(m, 0.0f));
            while (lo < hi) {
                unsigned mid = lo + ((hi - lo + 1u) >> 1);
                float thr = __uint_as_float(mid);
                int cc = 0;
                for (int i = tid; i < P; i += TPB) cc += (row[i] >= thr);
                si[tid] = cc; __syncthreads();
                for (int o = TPB / 2; o; o >>= 1) { if (tid < o) si[tid] += si[tid + o]; __syncthreads(); }
                int cge = si[0];
                __syncthreads();
                if ((long)cge >= k) lo = mid; else hi = mid - 1u;
            }
            if (tid == 0) s_bits = lo;
            __syncthreads();
            float thr = __uint_as_float(s_bits);

            float sg = 0.0f; int cg = 0;
            for (int i = tid; i < P; i += TPB) {
                float v = row[i];
                if (v > thr) { sg += v; cg++; }
            }
            sf[tid] = sg; si[tid] = cg; __syncthreads();
            for (int o = TPB / 2; o; o >>= 1) {
                if (tid < o) { sf[tid] += sf[tid + o]; si[tid] += si[tid + o]; }
                __syncthreads();
            }
            neg = sf[0] + (float)(k - (long)si[0]) * thr;
            __syncthreads();
        }
    }

    // ---- publish; phase-2 ticket elects the final combiner ----
    if (tid == 0) {
        g_img_loss[b] = pos_loss + neg;
        g_img_pos[b] = np;
        __threadfence();
        int t2 = atomicAdd(&g_done2, 1);
        s_last = (t2 == B - 1) ? 1 : 0;
    }
    __syncthreads();
    if (!s_last) return;

    // all 64 epilogue CTAs have published: combine, write scalar, reset tickets.
    {
        float ls = 0.0f; int lc = 0;
        if (tid < B) { ls = g_img_loss[tid]; lc = g_img_pos[tid]; }
        sf[tid] = ls; si[tid] = lc; __syncthreads();
        #pragma unroll
        for (int o = TPB / 2; o; o >>= 1) {
            if (tid < o) { sf[tid] += sf[tid + o]; si[tid] += si[tid + o]; }
            __syncthreads();
        }
        if (tid == 0) {
            float N = (float)(si[0] > 0 ? si[0] : 1);
            out[0] = sf[0] / N;
            atomicExch(&g_tile_ctr, 0);   // reset work counter for next graph replay
            atomicExch(&g_done, 0);
            atomicExch(&g_done2, 0);
        }
    }
}

// ---------------- launch ----------------
extern "C" void kernel_launch(void* const* d_in, const int* in_sizes, int n_in,
                              void* d_out, int out_size) {
    const float* loc_preds   = (const float*)d_in[0];
    const float* cls_preds   = (const float*)d_in[1];
    const float* loc_targets = (const float*)d_in[2];
    const int*   cls_targets = (const int*)d_in[3];
    float* out = (float*)d_out;

    k_ssd<<<NBLK, TPB>>>(loc_preds, cls_preds, loc_targets, cls_targets, out);
}

// round 15
// speedup vs baseline: 1.2572x; 1.2572x over previous
#include <cuda_runtime.h>
#include <cuda_bf16.h>

// ---------------- problem constants (from reference setup_inputs) ----------------
constexpr int B = 64;
constexpr int P = 24576;
constexpr int C = 81;            // NUM_CLASSES + 1
constexpr int NEG_POS_RATIO = 3;

constexpr int TPB = 128;                 // threads per block
constexpr int APB = 64;                  // anchors per tile (2 threads/anchor)
constexpr int NT  = (B * P) / APB;       // 24576 tiles
constexpr int TPI = P / APB;             // 384 tiles per image (tiles never straddle images)
constexpr int TILE_F  = APB * C;         // 5184 floats per tile
constexpr int TILE_F4 = TILE_F / 4;      // 1296 float4
constexpr int NBLK = 740;                // persistent CTAs: 148 SMs x 5 (exactly one wave)

// ---------------- scratch (device globals; no allocation allowed) ----------------
__device__ float g_ce_neg[B * P];   // scratch for fallback path ONLY (filled on demand)
__device__ float g_pos[NT];         // per-tile positive loss (ce + huber)  [distinct addrs]
__device__ float g_negp[NT];        // per-tile negative-CE sum
__device__ int   g_cnt[NT];         // per-tile positive counts
__device__ float g_img_loss[B];
__device__ int   g_img_pos[B];
__device__ int   g_done;            // phase-1 arrival ticket (reset each run)
__device__ int   g_done2;           // phase-2 arrival ticket (reset each run)

// ---------------- helpers ----------------
__device__ __forceinline__ float huber1(float d) {
    float ad = fabsf(d);
    return ad < 1.0f ? 0.5f * d * d : ad - 0.5f;
}
__device__ __forceinline__ void cp_async16(void* smem_dst, const void* gmem_src) {
    unsigned sa = (unsigned)__cvta_generic_to_shared(smem_dst);
    asm volatile("cp.async.cg.shared.global [%0], [%1], 16;" :: "r"(sa), "l"(gmem_src));
}
__device__ __forceinline__ void cp_commit() { asm volatile("cp.async.commit_group;"); }
__device__ __forceinline__ void cp_wait1()  { asm volatile("cp.async.wait_group 1;"); }

// ---------------- single persistent kernel -----------------------------------------
__global__ void __launch_bounds__(TPB) k_ssd(
    const float* __restrict__ loc_preds,
    const float* __restrict__ cls_preds,
    const float* __restrict__ loc_targets,
    const int*   __restrict__ cls_targets,
    float* __restrict__ out)
{
    __shared__ float buf[2][TILE_F];     // 2 x 20736 B
    __shared__ int   s_tgt[2][APB];
    __shared__ float s_part[TPB];
    __shared__ float s_xt[APB];
    __shared__ float swp[2], swn[2];
    __shared__ int   swc[2];
    __shared__ int   s_last;

    const int tid  = threadIdx.x;
    const int lane = tid & 31;
    const int wid  = tid >> 5;
    const int a    = tid & (APB - 1);
    const int h    = tid >> 6;           // class-half: 0 -> [0,41), 1 -> [41,81)

    auto stage = [&](int tile, int s) {
        const float4* __restrict__ src =
            reinterpret_cast<const float4*>(cls_preds + (long)tile * TILE_F);
        float4* dst = reinterpret_cast<float4*>(buf[s]);
        #pragma unroll
        for (int it = 0; it < 11; it++) {
            int idx = tid + it * TPB;
            if (idx < TILE_F4) cp_async16(&dst[idx], &src[idx]);
        }
        if (tid < APB / 4) {
            const int4* ts = reinterpret_cast<const int4*>(cls_targets + (long)tile * APB);
            cp_async16(&reinterpret_cast<int4*>(s_tgt[s])[tid], &ts[tid]);
        }
    };

    int tile = blockIdx.x;
    if (tile < NT) stage(tile, 0);
    cp_commit();

    int cur = 0;
    for (; tile < NT; tile += NBLK) {
        const int nxt = tile + NBLK;
        if (nxt < NT) stage(nxt, cur ^ 1);
        cp_commit();
        cp_wait1();
        __syncthreads();

        const long ag = (long)tile * APB + a;
        const int t = s_tgt[cur][a];

        float4 lp, lt;
        if (h == 0) {
            lp = reinterpret_cast<const float4*>(loc_preds)[ag];
            lt = reinterpret_cast<const float4*>(loc_targets)[ag];
        }

        const float* __restrict__ row = buf[cur] + a * C;  // stride 81: conflict-free
        float e0 = 0.0f, e1 = 0.0f;
        if (h == 0) {
            #pragma unroll
            for (int c = 0; c < 40; c += 2) { e0 += __expf(row[c]); e1 += __expf(row[c + 1]); }
            e0 += __expf(row[40]);
            if (t <= 40) s_xt[a] = row[t];
        } else {
            #pragma unroll
            for (int c = 41; c < 81; c += 2) { e0 += __expf(row[c]); e1 += __expf(row[c + 1]); }
            if (t > 40) s_xt[a] = row[t];
        }
        s_part[tid] = e0 + e1;
        __syncthreads();

        float accp = 0.0f, accn = 0.0f;
        int cnt = 0;
        if (h == 0) {
            const float s  = s_part[a] + s_part[a + APB];
            const float ce = __logf(s) - s_xt[a];
            const bool pos = (t > 0);
            // NOTE: no per-anchor CE store here; fallback path recomputes on demand
            if (pos) {
                accp = ce + huber1(lp.x - lt.x) + huber1(lp.y - lt.y) +
                            huber1(lp.z - lt.z) + huber1(lp.w - lt.w);
                cnt = 1;
            } else {
                accn = ce;
            }
            #pragma unroll
            for (int o = 16; o; o >>= 1) {
                accp += __shfl_down_sync(0xFFFFFFFFu, accp, o);
                accn += __shfl_down_sync(0xFFFFFFFFu, accn, o);
                cnt  += __shfl_down_sync(0xFFFFFFFFu, cnt,  o);
            }
            if (lane == 0) { swp[wid] = accp; swn[wid] = accn; swc[wid] = cnt; }
        }
        __syncthreads();
        if (tid == 0) {                       // distinct addresses: plain stores
            g_pos[tile]  = swp[0] + swp[1];
            g_negp[tile] = swn[0] + swn[1];
            g_cnt[tile]  = swc[0] + swc[1];
        }
        __syncthreads();
        cur ^= 1;
    }

    // ---- phase-1 ticket: all CTAs announce completion ----
    if (tid == 0) {
        __threadfence();
        atomicAdd(&g_done, 1);
    }
    if (blockIdx.x >= B) return;             // only CTAs 0..63 continue

    // ---- grid barrier (safe: single wave, all 740 CTAs resident) ----
    if (tid == 0) {
        while (atomicAdd(&g_done, 0) < NBLK) { }
        __threadfence();
    }
    __syncthreads();

    // ================= per-image epilogue: CTA b handles image b =================
    const int b = blockIdx.x;

    __shared__ float sf[TPB];
    __shared__ float sn[TPB];
    __shared__ int   si[TPB];
    __shared__ unsigned s_bits;

    float p = 0.0f, n = 0.0f; int c = 0;
    #pragma unroll
    for (int i = tid; i < TPI; i += TPB) {   // 3 iterations, L2-hot
        int idx = b * TPI + i;
        p += g_pos[idx]; n += g_negp[idx]; c += g_cnt[idx];
    }
    sf[tid] = p; sn[tid] = n; si[tid] = c; __syncthreads();
    #pragma unroll
    for (int o = TPB / 2; o; o >>= 1) {
        if (tid < o) { sf[tid] += sf[tid + o]; sn[tid] += sn[tid + o]; si[tid] += si[tid + o]; }
        __syncthreads();
    }
    const float pos_loss = sf[0];
    float neg = sn[0];
    const int np = si[0];
    __syncthreads();

    const long negc = (long)P - np;
    const long k = min((long)NEG_POS_RATIO * (long)np, negc);

    if (k < negc) {   // general path (not taken on this data); exact tie-corrected top-k
        float* row = g_ce_neg + (size_t)b * P;
        if (k <= 0) {
            neg = 0.0f;
        } else {
            // recompute this image's CE values into scratch (fallback only;
            // same formula as the hot loop so results are identical)
            const float* __restrict__ cp = cls_preds + (size_t)b * P * C;
            const int*   __restrict__ ct = cls_targets + (size_t)b * P;
            for (int i = tid; i < P; i += TPB) {
                const float* r = cp + (size_t)i * C;
                float s0 = 0.0f, s1 = 0.0f;
                #pragma unroll
                for (int cc = 0; cc < 80; cc += 2) { s0 += __expf(r[cc]); s1 += __expf(r[cc + 1]); }
                s0 += __expf(r[80]);
                const int t = ct[i];
                const float ce = __logf(s0 + s1) - r[t];
                row[i] = (t > 0) ? 0.0f : ce;
            }
            __syncthreads();

            float m = 0.0f;
            for (int i = tid; i < P; i += TPB) m = fmaxf(m, row[i]);
            sf[tid] = m; __syncthreads();
            for (int o = TPB / 2; o; o >>= 1) { if (tid < o) sf[tid] = fmaxf(sf[tid], sf[tid + o]); __syncthreads(); }
            m = sf[0];
            __syncthreads();

            unsigned lo = 0u, hi = __float_as_uint(fmaxf(m, 0.0f));
            while (lo < hi) {
                unsigned mid = lo + ((hi - lo + 1u) >> 1);
                float thr = __uint_as_float(mid);
                int cc = 0;
                for (int i = tid; i < P; i += TPB) cc += (row[i] >= thr);
                si[tid] = cc; __syncthreads();
                for (int o = TPB / 2; o; o >>= 1) { if (tid < o) si[tid] += si[tid + o]; __syncthreads(); }
                int cge = si[0];
                __syncthreads();
                if ((long)cge >= k) lo = mid; else hi = mid - 1u;
            }
            if (tid == 0) s_bits = lo;
            __syncthreads();
            float thr = __uint_as_float(s_bits);

            float sg = 0.0f; int cg = 0;
            for (int i = tid; i < P; i += TPB) {
                float v = row[i];
                if (v > thr) { sg += v; cg++; }
            }
            sf[tid] = sg; si[tid] = cg; __syncthreads();
            for (int o = TPB / 2; o; o >>= 1) {
                if (tid < o) { sf[tid] += sf[tid + o]; si[tid] += si[tid + o]; }
                __syncthreads();
            }
            neg = sf[0] + (float)(k - (long)si[0]) * thr;
            __syncthreads();
        }
    }

    // ---- publish; phase-2 ticket elects the final combiner ----
    if (tid == 0) {
        g_img_loss[b] = pos_loss + neg;
        g_img_pos[b] = np;
        __threadfence();
        int t2 = atomicAdd(&g_done2, 1);
        s_last = (t2 == B - 1) ? 1 : 0;
    }
    __syncthreads();
    if (!s_last) return;

    // all 64 epilogue CTAs have published: combine, write scalar, reset tickets.
    {
        float ls = 0.0f; int lc = 0;
        if (tid < B) { ls = g_img_loss[tid]; lc = g_img_pos[tid]; }
        sf[tid] = ls; si[tid] = lc; __syncthreads();
        #pragma unroll
        for (int o = TPB / 2; o; o >>= 1) {
            if (tid < o) { sf[tid] += sf[tid + o]; si[tid] += si[tid + o]; }
            __syncthreads();
        }
        if (tid == 0) {
            float N = (float)(si[0] > 0 ? si[0] : 1);
            out[0] = sf[0] / N;
            atomicExch(&g_done, 0);
            atomicExch(&g_done2, 0);
        }
    }
}

// ---------------- launch ----------------
extern "C" void kernel_launch(void* const* d_in, const int* in_sizes, int n_in,
                              void* d_out, int out_size) {
    const float* loc_preds   = (const float*)d_in[0];
    const float* cls_preds   = (const float*)d_in[1];
    const float* loc_targets = (const float*)d_in[2];
    const int*   cls_targets = (const int*)d_in[3];
    float* out = (float*)d_out;

    k_ssd<<<NBLK, TPB>>>(loc_preds, cls_preds, loc_targets, cls_targets, out);
}